// round 12
// baseline (speedup 1.0000x reference)
#include <cuda_runtime.h>
#include <cuda_fp16.h>
#include <math.h>
#include <stdint.h>

#define Bb  4
#define Ss  2048
#define Dd  1024
#define Hh  16
#define HDd 64
#define Mm  (Bb*Ss)   // 8192

// ---------------------------------------------------------------------------
// Scratch (device globals: allocation-free per harness rules)
// ---------------------------------------------------------------------------
__device__ __half g_xh[(size_t)Mm * Dd];
__device__ __half g_xl[(size_t)Mm * Dd];
__device__ __half g_w [(size_t)4 * Dd * Dd];
__device__ __half g_q [(size_t)Mm * Dd];
__device__ __half g_k [(size_t)Mm * Dd];
__device__ __half g_vt[(size_t)Mm * Dd];
__device__ __half g_c [(size_t)Mm * Dd];

// 0.125 * log2(e)  (folded into Q so softmax runs in exp2 domain)
#define QSCALE 0.18033688011112042f

// ---------------------------------------------------------------------------
// Helpers
// ---------------------------------------------------------------------------
__device__ __forceinline__ uint32_t smem_u32(const void* p) {
    uint32_t a;
    asm("{ .reg .u64 t; cvta.to.shared.u64 t, %1; cvt.u32.u64 %0, t; }"
        : "=r"(a) : "l"(p));
    return a;
}

__device__ __forceinline__ float ex2(float x) {
    float y;
    asm("ex2.approx.ftz.f32 %0, %1;" : "=f"(y) : "f"(x));
    return y;
}

__device__ __forceinline__ void ldsm_x4(uint32_t addr, uint32_t* r) {
    asm volatile("ldmatrix.sync.aligned.m8n8.x4.shared.b16 {%0,%1,%2,%3}, [%4];"
        : "=r"(r[0]), "=r"(r[1]), "=r"(r[2]), "=r"(r[3]) : "r"(addr));
}

__device__ __forceinline__ void mma16816h(float* c, const uint32_t* a, const uint32_t* b) {
    asm volatile(
        "mma.sync.aligned.m16n8k16.row.col.f32.f16.f16.f32 "
        "{%0,%1,%2,%3}, {%4,%5,%6,%7}, {%8,%9}, {%0,%1,%2,%3};"
        : "+f"(c[0]), "+f"(c[1]), "+f"(c[2]), "+f"(c[3])
        : "r"(a[0]), "r"(a[1]), "r"(a[2]), "r"(a[3]), "r"(b[0]), "r"(b[1]));
}

__device__ __forceinline__ uint32_t pack_h2(float a, float b) {
    __half2 h = __floats2half2_rn(a, b);
    return *(uint32_t*)&h;
}

// split one float into fp16 hi + fp16 lo (residual)
__device__ __forceinline__ void split1(float v, __half& h, __half& l) {
    h = __float2half_rn(v);
    l = __float2half_rn(v - __half2float(h));
}

__device__ __forceinline__ void cp16(uint32_t dst, const void* src) {
    asm volatile("cp.async.cg.shared.global [%0], [%1], 16;" :: "r"(dst), "l"(src));
}
#define CP_COMMIT() asm volatile("cp.async.commit_group;" ::: "memory")
#define CP_WAIT2()  asm volatile("cp.async.wait_group 2;" ::: "memory")
#define CP_WAIT1()  asm volatile("cp.async.wait_group 1;" ::: "memory")
#define CP_WAIT0()  asm volatile("cp.async.wait_group 0;" ::: "memory")

// ---------------------------------------------------------------------------
// Conversions: x -> fp16 hi/lo ; 4 weights -> fp16 (one launch)
// ---------------------------------------------------------------------------
__global__ __launch_bounds__(256)
void split_x(const float4* __restrict__ in, uint2* __restrict__ hi,
             uint2* __restrict__ lo, int n4)
{
    int i = blockIdx.x * blockDim.x + threadIdx.x;
    if (i < n4) {
        float4 v = in[i];
        __half h0, h1, h2, h3, l0, l1, l2, l3;
        split1(v.x, h0, l0); split1(v.y, h1, l1);
        split1(v.z, h2, l2); split1(v.w, h3, l3);
        __half2 ha = __halves2half2(h0, h1), hb = __halves2half2(h2, h3);
        __half2 la = __halves2half2(l0, l1), lb = __halves2half2(l2, l3);
        hi[i] = make_uint2(*(uint32_t*)&ha, *(uint32_t*)&hb);
        lo[i] = make_uint2(*(uint32_t*)&la, *(uint32_t*)&lb);
    }
}

__global__ __launch_bounds__(256)
void cast_w4(const float4* __restrict__ w0, const float4* __restrict__ w1,
             const float4* __restrict__ w2, const float4* __restrict__ w3,
             uint2* __restrict__ wp, int n4)
{
    int i = blockIdx.x * blockDim.x + threadIdx.x;
    int m = blockIdx.y;
    if (i < n4) {
        const float4* src = (m == 0) ? w0 : (m == 1) ? w1 : (m == 2) ? w2 : w3;
        float4 v = src[i];
        __half2 a = __floats2half2_rn(v.x, v.y);
        __half2 b = __floats2half2_rn(v.z, v.w);
        wp[(size_t)m * n4 + i] = make_uint2(*(uint32_t*)&a, *(uint32_t*)&b);
    }
}

// ---------------------------------------------------------------------------
// HMMA GEMM: C[M,N] = A[M,K] @ W[N,K]^T + bias
//   TWOPASS=1: A as hi/lo fp16 (2-pass). TWOPASS=0: plain fp16 single pass.
// 128x128 CTA tile, 512 threads, KC=64, 3-stage cp.async (prefetch depth 2).
// FUSED=1: N=3072 fused QKV; epilogue by matrix (Q scaled fp16, K fp16, V^T).
// FUSED=0: fp32 [M,1024] out + bias0.
// ---------------------------------------------------------------------------
#define GKC 64
#define NCH (Dd / GKC)          // 16
#define MROW 144                // bytes per smem row (64 halves + 16B pad)
#define MAT_BYTES (128 * MROW)  // 18432
#define STAGE (3 * MAT_BYTES)   // 55296
#define GSMEM (3 * STAGE)       // 165888

template <int TWOPASS>
__device__ __forceinline__ void gemm_issue(
    uint32_t st, int tid, int m0, int n0, int k0,
    const __half* __restrict__ Ah, const __half* __restrict__ Al,
    const __half* __restrict__ Bh)
{
#pragma unroll
    for (int i = 0; i < 2; i++) {
        int idx = tid + i * 512;
        int r = idx >> 3;               // 0..127
        int c8 = (idx & 7) * 8;         // halves offset
        const uint32_t d = st + r * MROW + c8 * 2;
        const size_t offA = (size_t)(m0 + r) * Dd + k0 + c8;
        cp16(d, Ah + offA);
        if (TWOPASS) cp16(d + MAT_BYTES, Al + offA);
        cp16(d + 2 * MAT_BYTES, Bh + (size_t)(n0 + r) * Dd + k0 + c8);
    }
    CP_COMMIT();
}

template <int FUSED, int TWOPASS>
__global__ __launch_bounds__(512)
void gemm_tc(const __half* __restrict__ Ah, const __half* __restrict__ Al,
             const __half* __restrict__ Bh,
             const float* __restrict__ bias0, const float* __restrict__ bias1,
             const float* __restrict__ bias2,
             __half* __restrict__ o_q, __half* __restrict__ o_k,
             __half* __restrict__ o_vt, float* __restrict__ o_f32)
{
    extern __shared__ char sm[];
    const uint32_t sbase = smem_u32(sm);

    const int tid  = threadIdx.x;
    const int wid  = tid >> 5;
    const int lane = tid & 31;
    const int m0 = blockIdx.y * 128;
    const int n0 = blockIdx.x * 128;
    const int wm = (wid & 3) * 32;
    const int wn = (wid >> 2) * 32;

    float acc[2][4][4];
#pragma unroll
    for (int mt = 0; mt < 2; mt++)
#pragma unroll
        for (int nt = 0; nt < 4; nt++)
#pragma unroll
            for (int i = 0; i < 4; i++) acc[mt][nt][i] = 0.f;

    const int a_r = lane & 15;
    const int a_k16 = (lane >> 4) * 16;               // byte offset
    const int b_r = (lane & 7) + ((lane >> 4) << 3);
    const int b_k16 = (lane & 8) ? 16 : 0;            // byte offset

    gemm_issue<TWOPASS>(sbase,         tid, m0, n0, 0,   Ah, Al, Bh);
    gemm_issue<TWOPASS>(sbase + STAGE, tid, m0, n0, GKC, Ah, Al, Bh);

    for (int c = 0; c < NCH; c++) {
        const int s = c % 3;
        if (c + 2 < NCH) {
            gemm_issue<TWOPASS>(sbase + ((c + 2) % 3) * STAGE, tid, m0, n0,
                                (c + 2) * GKC, Ah, Al, Bh);
            CP_WAIT2();
        } else if (c + 1 < NCH) {
            CP_WAIT1();
        } else {
            CP_WAIT0();
        }
        __syncthreads();

        const uint32_t st = sbase + s * STAGE;
#pragma unroll
        for (int ks = 0; ks < 4; ks++) {
            uint32_t af[2][4], alf[2][4], bf[2][4];
#pragma unroll
            for (int mt = 0; mt < 2; mt++) {
                uint32_t addr = st + (wm + mt * 16 + a_r) * MROW + ks * 32 + a_k16;
                ldsm_x4(addr, af[mt]);
                if (TWOPASS) ldsm_x4(addr + MAT_BYTES, alf[mt]);
            }
#pragma unroll
            for (int nq = 0; nq < 2; nq++) {
                uint32_t addr = st + 2 * MAT_BYTES
                              + (wn + nq * 16 + b_r) * MROW + ks * 32 + b_k16;
                ldsm_x4(addr, bf[nq]);
            }
#pragma unroll
            for (int mt = 0; mt < 2; mt++)
#pragma unroll
                for (int nt = 0; nt < 4; nt++) {
                    const uint32_t* bh = &bf[nt >> 1][(nt & 1) * 2];
                    mma16816h(acc[mt][nt], af[mt], bh);               // Ah*B
                    if (TWOPASS) mma16816h(acc[mt][nt], alf[mt], bh); // Al*B
                }
        }
        __syncthreads();
    }

    // Epilogue
    const int matrix = FUSED ? (n0 >> 10) : 0;
    const float* bias = FUSED ? (matrix == 0 ? bias0 : (matrix == 1 ? bias1 : bias2))
                              : bias0;
    const int tg = lane >> 2;
    const int tc = (lane & 3) * 2;
#pragma unroll
    for (int mt = 0; mt < 2; mt++) {
#pragma unroll
        for (int nt = 0; nt < 4; nt++) {
            const int n = n0 + wn + nt * 8 + tc;
            const int nl = n & 1023;
            const float b0 = bias[nl], b1 = bias[nl + 1];
#pragma unroll
            for (int hf = 0; hf < 2; hf++) {
                const int m = m0 + wm + mt * 16 + tg + hf * 8;
                float v0 = acc[mt][nt][hf * 2 + 0] + b0;
                float v1 = acc[mt][nt][hf * 2 + 1] + b1;
                if (!FUSED) {
                    *(float2*)(o_f32 + (size_t)m * Dd + n) = make_float2(v0, v1);
                } else {
                    const int bi = m >> 11, sr = m & 2047;
                    const int hh = nl >> 6, hd = nl & 63;
                    if (matrix == 0) {          // Q: scaled, plain fp16
                        v0 *= QSCALE; v1 *= QSCALE;
                        const size_t a = (((size_t)(bi * Hh + hh)) * Ss + sr) * HDd + hd;
                        __half2 ph = __floats2half2_rn(v0, v1);
                        *(uint32_t*)(o_q + a) = *(uint32_t*)&ph;
                    } else if (matrix == 1) {   // K: fp16
                        const size_t a = (((size_t)(bi * Hh + hh)) * Ss + sr) * HDd + hd;
                        __half2 ph = __floats2half2_rn(v0, v1);
                        *(uint32_t*)(o_k + a) = *(uint32_t*)&ph;
                    } else {                    // V: fp16 transposed [B,H,HD,S]
                        const size_t a = (((size_t)(bi * Hh + hh)) * HDd + hd) * Ss + sr;
                        o_vt[a]      = __float2half(v0);
                        o_vt[a + Ss] = __float2half(v1);
                    }
                }
            }
        }
    }
}

// ---------------------------------------------------------------------------
// Tensor-core flash attention (single-pass fp16 QK^T; 2 CTAs/SM).
// CTA: 128 q rows; 8 warps x 16 q rows. KV tile 128.
// Softmax in c-frags, exp2 domain (scale folded into Q).
// ctx written as plain fp16 [B,S,D].
// ---------------------------------------------------------------------------
#define QROW 144
#define VROW 272
#define QMAT (128 * QROW)
#define KMAT (128 * QROW)
#define VMAT (64 * VROW)
#define STAGEA (KMAT + VMAT)
#define ATT_SMEM (QMAT + 2 * STAGEA)  // 90112

__device__ __forceinline__ void attn_load_kv(
    uint32_t st, int tid, int kv0,
    const __half* __restrict__ kp, const __half* __restrict__ vt,
    size_t qkbase, size_t vbase)
{
#pragma unroll
    for (int i = 0; i < 4; i++) {
        int idx = tid + i * 256;
        int r = idx >> 3, c = (idx & 7) * 8;
        cp16(st + r * QROW + c * 2, kp + qkbase + (size_t)(kv0 + r) * HDd + c);
    }
#pragma unroll
    for (int i = 0; i < 4; i++) {
        int idx = tid + i * 256;
        int r = idx >> 4, c = (idx & 15) * 8;
        cp16(st + KMAT + r * VROW + c * 2, vt + vbase + (size_t)r * Ss + kv0 + c);
    }
}

__global__ __launch_bounds__(256, 2)
void attn_tc(const __half* __restrict__ qp, const __half* __restrict__ kp,
             const __half* __restrict__ vt, __half* __restrict__ cp)
{
    extern __shared__ char sm[];
    const uint32_t sb = smem_u32(sm);
    const int tid = threadIdx.x;
    const int w = tid >> 5, lane = tid & 31;
    const int q0 = blockIdx.x * 128;
    const int h = blockIdx.y, b = blockIdx.z;
    const size_t qkbase = ((size_t)(b * Hh + h) * Ss) * HDd;
    const size_t vbase  = ((size_t)(b * Hh + h) * HDd) * Ss;

    // Prologue: Q (resident in smem) + KV tile 0
#pragma unroll
    for (int i = 0; i < 4; i++) {
        int idx = tid + i * 256;
        int r = idx >> 3, c = (idx & 7) * 8;
        cp16(sb + r * QROW + c * 2, qp + qkbase + (size_t)(q0 + r) * HDd + c);
    }
    attn_load_kv(sb + QMAT, tid, 0, kp, vt, qkbase, vbase);
    CP_COMMIT();

    const int a_r = lane & 15;
    const int a_k = (lane >> 4) * 8;
    const int b_r = (lane & 7) + ((lane >> 4) << 3);
    const int b_k = (lane & 8) ? 8 : 0;

    float o[8][4];
#pragma unroll
    for (int nt = 0; nt < 8; nt++)
#pragma unroll
        for (int i = 0; i < 4; i++) o[nt][i] = 0.f;
    float m2[2] = {-1e30f, -1e30f};
    float lsum[2] = {0.f, 0.f};

    for (int t = 0; t < Ss / 128; t++) {
        const int s = t & 1;
        const uint32_t stc = sb + QMAT + s * STAGEA;
        if (t + 1 < Ss / 128) {
            attn_load_kv(sb + QMAT + (s ^ 1) * STAGEA, tid, (t + 1) * 128,
                         kp, vt, qkbase, vbase);
            CP_COMMIT();
            CP_WAIT1();
        } else {
            CP_WAIT0();
        }
        __syncthreads();

        // ---- scores S = Q K^T (single-pass fp16) ----
        float sc[16][4];
#pragma unroll
        for (int nt = 0; nt < 16; nt++)
#pragma unroll
            for (int i = 0; i < 4; i++) sc[nt][i] = 0.f;

#pragma unroll
        for (int kc = 0; kc < 4; kc++) {
            uint32_t qf[4];
            ldsm_x4(sb + (w * 16 + a_r) * QROW + (kc * 16 + a_k) * 2, qf);
#pragma unroll
            for (int g = 0; g < 8; g++) {
                uint32_t bh[4];
                uint32_t ad = stc + (g * 16 + b_r) * QROW + (kc * 16 + b_k) * 2;
                ldsm_x4(ad, bh);
                mma16816h(sc[2 * g],     qf, bh);
                mma16816h(sc[2 * g + 1], qf, bh + 2);
            }
        }

        // ---- online softmax (exp2 domain; rows split over 4-lane groups) ----
#pragma unroll
        for (int rh = 0; rh < 2; rh++) {
            const int c0 = rh * 2;
            float mx = -1e30f;
#pragma unroll
            for (int nt = 0; nt < 16; nt++)
                mx = fmaxf(mx, fmaxf(sc[nt][c0], sc[nt][c0 + 1]));
            mx = fmaxf(mx, __shfl_xor_sync(0xffffffffu, mx, 1));
            mx = fmaxf(mx, __shfl_xor_sync(0xffffffffu, mx, 2));
            float mn = fmaxf(m2[rh], mx);
            float al = ex2(m2[rh] - mn);
            m2[rh] = mn;
            float rs = 0.f;
#pragma unroll
            for (int nt = 0; nt < 16; nt++) {
                sc[nt][c0]     = ex2(sc[nt][c0] - mn);
                sc[nt][c0 + 1] = ex2(sc[nt][c0 + 1] - mn);
                rs += sc[nt][c0] + sc[nt][c0 + 1];
            }
            rs += __shfl_xor_sync(0xffffffffu, rs, 1);
            rs += __shfl_xor_sync(0xffffffffu, rs, 2);
            lsum[rh] = lsum[rh] * al + rs;
#pragma unroll
            for (int nt = 0; nt < 8; nt++) {
                o[nt][c0]     *= al;
                o[nt][c0 + 1] *= al;
            }
        }

        // ---- P (c-frag) -> fp16 A-frags, register-only ----
        uint32_t pa[8][4];
#pragma unroll
        for (int kc = 0; kc < 8; kc++) {
            pa[kc][0] = pack_h2(sc[2 * kc][0],     sc[2 * kc][1]);
            pa[kc][1] = pack_h2(sc[2 * kc][2],     sc[2 * kc][3]);
            pa[kc][2] = pack_h2(sc[2 * kc + 1][0], sc[2 * kc + 1][1]);
            pa[kc][3] = pack_h2(sc[2 * kc + 1][2], sc[2 * kc + 1][3]);
        }

        // ---- O += P V (fp16) ----
        const uint32_t vs = stc + KMAT;
#pragma unroll
        for (int g = 0; g < 4; g++) {
#pragma unroll
            for (int kc = 0; kc < 8; kc++) {
                uint32_t vb[4];
                ldsm_x4(vs + (g * 16 + b_r) * VROW + (kc * 16 + b_k) * 2, vb);
                mma16816h(o[2 * g],     pa[kc], vb);
                mma16816h(o[2 * g + 1], pa[kc], vb + 2);
            }
        }
        __syncthreads();
    }

    // ---- epilogue: ctx = O/l as plain fp16, [B,S,D] layout ----
    const int tg = lane >> 2;
    const int tc2 = (lane & 3) * 2;
#pragma unroll
    for (int rh = 0; rh < 2; rh++) {
        float inv = 1.f / lsum[rh];
        int srow = q0 + w * 16 + tg + rh * 8;
#pragma unroll
        for (int nt = 0; nt < 8; nt++) {
            float v0 = o[nt][rh * 2] * inv;
            float v1 = o[nt][rh * 2 + 1] * inv;
            __half2 ph = __floats2half2_rn(v0, v1);
            size_t a = ((size_t)b * Ss + srow) * Dd + h * HDd + nt * 8 + tc2;
            *(uint32_t*)(cp + a) = *(uint32_t*)&ph;
        }
    }
}

// ---------------------------------------------------------------------------
extern "C" void kernel_launch(void* const* d_in, const int* in_sizes, int n_in,
                              void* d_out, int out_size)
{
    const float* x  = (const float*)d_in[0];
    const float* Wq = (const float*)d_in[1];
    const float* bq = (const float*)d_in[2];
    const float* Wk = (const float*)d_in[3];
    const float* bk = (const float*)d_in[4];
    const float* Wv = (const float*)d_in[5];
    const float* bv = (const float*)d_in[6];
    const float* Wo = (const float*)d_in[7];
    const float* bo = (const float*)d_in[8];
    float* out = (float*)d_out;

    __half *xh, *xl, *wp, *qp, *kpp, *vtp, *cpp;
    cudaGetSymbolAddress((void**)&xh,  g_xh);
    cudaGetSymbolAddress((void**)&xl,  g_xl);
    cudaGetSymbolAddress((void**)&wp,  g_w);
    cudaGetSymbolAddress((void**)&qp,  g_q);
    cudaGetSymbolAddress((void**)&kpp, g_k);
    cudaGetSymbolAddress((void**)&vtp, g_vt);
    cudaGetSymbolAddress((void**)&cpp, g_c);

    cudaFuncSetAttribute((const void*)gemm_tc<1, 1>,
                         cudaFuncAttributeMaxDynamicSharedMemorySize, GSMEM);
    cudaFuncSetAttribute((const void*)gemm_tc<0, 0>,
                         cudaFuncAttributeMaxDynamicSharedMemorySize, GSMEM);
    cudaFuncSetAttribute(attn_tc,
                         cudaFuncAttributeMaxDynamicSharedMemorySize, ATT_SMEM);

    // conversions
    const int nx4 = (Mm * Dd) / 4;
    const int nw4 = (Dd * Dd) / 4;
    split_x<<<nx4 / 256, 256>>>((const float4*)x, (uint2*)xh, (uint2*)xl, nx4);
    dim3 gw(nw4 / 256, 4);
    cast_w4<<<gw, 256>>>((const float4*)Wq, (const float4*)Wk,
                         (const float4*)Wv, (const float4*)Wo, (uint2*)wp, nw4);

    // fused QKV projection: N = 3072 (2-pass fp16)
    dim3 gf(3 * Dd / 128, Mm / 128);   // (24, 64)
    gemm_tc<1, 1><<<gf, 512, GSMEM>>>(xh, xl, wp, bq, bk, bv,
                                      qp, kpp, vtp, nullptr);

    // attention
    dim3 ga(Ss / 128, Hh, Bb);         // (16, 16, 4)
    attn_tc<<<ga, 256, ATT_SMEM>>>(qp, kpp, vtp, cpp);

    // output projection (single-pass fp16)
    dim3 go(Dd / 128, Mm / 128);       // (8, 64)
    gemm_tc<0, 0><<<go, 512, GSMEM>>>(cpp, nullptr, wp + 3 * (size_t)Dd * Dd,
                                      bo, nullptr, nullptr,
                                      nullptr, nullptr, nullptr, out);
}

// round 14
// speedup vs baseline: 1.4231x; 1.4231x over previous
#include <cuda_runtime.h>
#include <cuda_fp16.h>
#include <math.h>
#include <stdint.h>

#define Bb  4
#define Ss  2048
#define Dd  1024
#define Hh  16
#define HDd 64
#define Mm  (Bb*Ss)   // 8192

// ---------------------------------------------------------------------------
// Scratch (device globals: allocation-free per harness rules)
// ---------------------------------------------------------------------------
__device__ __half g_xh[(size_t)Mm * Dd];
__device__ __half g_xl[(size_t)Mm * Dd];
__device__ __half g_w [(size_t)4 * Dd * Dd];
__device__ __half g_qh[(size_t)Mm * Dd];
__device__ __half g_ql[(size_t)Mm * Dd];
__device__ __half g_k [(size_t)Mm * Dd];
__device__ __half g_vt[(size_t)Mm * Dd];
__device__ __half g_c [(size_t)Mm * Dd];

// 0.125 * log2(e)  (folded into Q so softmax runs in exp2 domain)
#define QSCALE 0.18033688011112042f

// ---------------------------------------------------------------------------
// Helpers
// ---------------------------------------------------------------------------
__device__ __forceinline__ uint32_t smem_u32(const void* p) {
    uint32_t a;
    asm("{ .reg .u64 t; cvta.to.shared.u64 t, %1; cvt.u32.u64 %0, t; }"
        : "=r"(a) : "l"(p));
    return a;
}

__device__ __forceinline__ float ex2(float x) {
    float y;
    asm("ex2.approx.ftz.f32 %0, %1;" : "=f"(y) : "f"(x));
    return y;
}

__device__ __forceinline__ void ldsm_x4(uint32_t addr, uint32_t* r) {
    asm volatile("ldmatrix.sync.aligned.m8n8.x4.shared.b16 {%0,%1,%2,%3}, [%4];"
        : "=r"(r[0]), "=r"(r[1]), "=r"(r[2]), "=r"(r[3]) : "r"(addr));
}

__device__ __forceinline__ void mma16816h(float* c, const uint32_t* a, const uint32_t* b) {
    asm volatile(
        "mma.sync.aligned.m16n8k16.row.col.f32.f16.f16.f32 "
        "{%0,%1,%2,%3}, {%4,%5,%6,%7}, {%8,%9}, {%0,%1,%2,%3};"
        : "+f"(c[0]), "+f"(c[1]), "+f"(c[2]), "+f"(c[3])
        : "r"(a[0]), "r"(a[1]), "r"(a[2]), "r"(a[3]), "r"(b[0]), "r"(b[1]));
}

__device__ __forceinline__ uint32_t pack_h2(float a, float b) {
    __half2 h = __floats2half2_rn(a, b);
    return *(uint32_t*)&h;
}

// split one float into fp16 hi + fp16 lo (residual)
__device__ __forceinline__ void split1(float v, __half& h, __half& l) {
    h = __float2half_rn(v);
    l = __float2half_rn(v - __half2float(h));
}

__device__ __forceinline__ void cp16(uint32_t dst, const void* src) {
    asm volatile("cp.async.cg.shared.global [%0], [%1], 16;" :: "r"(dst), "l"(src));
}
#define CP_COMMIT() asm volatile("cp.async.commit_group;" ::: "memory")
#define CP_WAIT2()  asm volatile("cp.async.wait_group 2;" ::: "memory")
#define CP_WAIT1()  asm volatile("cp.async.wait_group 1;" ::: "memory")
#define CP_WAIT0()  asm volatile("cp.async.wait_group 0;" ::: "memory")

// ---------------------------------------------------------------------------
// Conversions: x -> fp16 hi/lo ; 4 weights -> fp16 (one launch)
// ---------------------------------------------------------------------------
__global__ __launch_bounds__(256)
void split_x(const float4* __restrict__ in, uint2* __restrict__ hi,
             uint2* __restrict__ lo, int n4)
{
    int i = blockIdx.x * blockDim.x + threadIdx.x;
    if (i < n4) {
        float4 v = in[i];
        __half h0, h1, h2, h3, l0, l1, l2, l3;
        split1(v.x, h0, l0); split1(v.y, h1, l1);
        split1(v.z, h2, l2); split1(v.w, h3, l3);
        __half2 ha = __halves2half2(h0, h1), hb = __halves2half2(h2, h3);
        __half2 la = __halves2half2(l0, l1), lb = __halves2half2(l2, l3);
        hi[i] = make_uint2(*(uint32_t*)&ha, *(uint32_t*)&hb);
        lo[i] = make_uint2(*(uint32_t*)&la, *(uint32_t*)&lb);
    }
}

__global__ __launch_bounds__(256)
void cast_w4(const float4* __restrict__ w0, const float4* __restrict__ w1,
             const float4* __restrict__ w2, const float4* __restrict__ w3,
             uint2* __restrict__ wp, int n4)
{
    int i = blockIdx.x * blockDim.x + threadIdx.x;
    int m = blockIdx.y;
    if (i < n4) {
        const float4* src = (m == 0) ? w0 : (m == 1) ? w1 : (m == 2) ? w2 : w3;
        float4 v = src[i];
        __half2 a = __floats2half2_rn(v.x, v.y);
        __half2 b = __floats2half2_rn(v.z, v.w);
        wp[(size_t)m * n4 + i] = make_uint2(*(uint32_t*)&a, *(uint32_t*)&b);
    }
}

// ---------------------------------------------------------------------------
// HMMA GEMM: C[M,N] = A[M,K] @ W[N,K]^T + bias
//   TWOPASS=1: A as hi/lo fp16 (2-pass). TWOPASS=0: plain fp16 single pass.
// 128x128 CTA tile, 512 threads, KC=64, 3-stage cp.async (prefetch depth 2).
// FUSED=1: N=3072 fused QKV; epilogue by matrix (Q hi/lo scaled, K, V^T).
// FUSED=0: fp32 [M,1024] out + bias0.
// ---------------------------------------------------------------------------
#define GKC 64
#define NCH (Dd / GKC)          // 16
#define MROW 144                // bytes per smem row (64 halves + 16B pad)
#define MAT_BYTES (128 * MROW)  // 18432
#define STAGE (3 * MAT_BYTES)   // 55296
#define GSMEM (3 * STAGE)       // 165888

template <int TWOPASS>
__device__ __forceinline__ void gemm_issue(
    uint32_t st, int tid, int m0, int n0, int k0,
    const __half* __restrict__ Ah, const __half* __restrict__ Al,
    const __half* __restrict__ Bh)
{
#pragma unroll
    for (int i = 0; i < 2; i++) {
        int idx = tid + i * 512;
        int r = idx >> 3;               // 0..127
        int c8 = (idx & 7) * 8;         // halves offset
        const uint32_t d = st + r * MROW + c8 * 2;
        const size_t offA = (size_t)(m0 + r) * Dd + k0 + c8;
        cp16(d, Ah + offA);
        if (TWOPASS) cp16(d + MAT_BYTES, Al + offA);
        cp16(d + 2 * MAT_BYTES, Bh + (size_t)(n0 + r) * Dd + k0 + c8);
    }
    CP_COMMIT();
}

template <int FUSED, int TWOPASS>
__global__ __launch_bounds__(512)
void gemm_tc(const __half* __restrict__ Ah, const __half* __restrict__ Al,
             const __half* __restrict__ Bh,
             const float* __restrict__ bias0, const float* __restrict__ bias1,
             const float* __restrict__ bias2,
             __half* __restrict__ o_qh, __half* __restrict__ o_ql,
             __half* __restrict__ o_k,  __half* __restrict__ o_vt,
             float* __restrict__ o_f32)
{
    extern __shared__ char sm[];
    const uint32_t sbase = smem_u32(sm);

    const int tid  = threadIdx.x;
    const int wid  = tid >> 5;
    const int lane = tid & 31;
    const int m0 = blockIdx.y * 128;
    const int n0 = blockIdx.x * 128;
    const int wm = (wid & 3) * 32;
    const int wn = (wid >> 2) * 32;

    float acc[2][4][4];
#pragma unroll
    for (int mt = 0; mt < 2; mt++)
#pragma unroll
        for (int nt = 0; nt < 4; nt++)
#pragma unroll
            for (int i = 0; i < 4; i++) acc[mt][nt][i] = 0.f;

    const int a_r = lane & 15;
    const int a_k16 = (lane >> 4) * 16;               // byte offset
    const int b_r = (lane & 7) + ((lane >> 4) << 3);
    const int b_k16 = (lane & 8) ? 16 : 0;            // byte offset

    gemm_issue<TWOPASS>(sbase,         tid, m0, n0, 0,   Ah, Al, Bh);
    gemm_issue<TWOPASS>(sbase + STAGE, tid, m0, n0, GKC, Ah, Al, Bh);

    for (int c = 0; c < NCH; c++) {
        const int s = c % 3;
        if (c + 2 < NCH) {
            gemm_issue<TWOPASS>(sbase + ((c + 2) % 3) * STAGE, tid, m0, n0,
                                (c + 2) * GKC, Ah, Al, Bh);
            CP_WAIT2();
        } else if (c + 1 < NCH) {
            CP_WAIT1();
        } else {
            CP_WAIT0();
        }
        __syncthreads();

        const uint32_t st = sbase + s * STAGE;
#pragma unroll
        for (int ks = 0; ks < 4; ks++) {
            uint32_t af[2][4], alf[2][4], bf[2][4];
#pragma unroll
            for (int mt = 0; mt < 2; mt++) {
                uint32_t addr = st + (wm + mt * 16 + a_r) * MROW + ks * 32 + a_k16;
                ldsm_x4(addr, af[mt]);
                if (TWOPASS) ldsm_x4(addr + MAT_BYTES, alf[mt]);
            }
#pragma unroll
            for (int nq = 0; nq < 2; nq++) {
                uint32_t addr = st + 2 * MAT_BYTES
                              + (wn + nq * 16 + b_r) * MROW + ks * 32 + b_k16;
                ldsm_x4(addr, bf[nq]);
            }
#pragma unroll
            for (int mt = 0; mt < 2; mt++)
#pragma unroll
                for (int nt = 0; nt < 4; nt++) {
                    const uint32_t* bh = &bf[nt >> 1][(nt & 1) * 2];
                    mma16816h(acc[mt][nt], af[mt], bh);               // Ah*B
                    if (TWOPASS) mma16816h(acc[mt][nt], alf[mt], bh); // Al*B
                }
        }
        __syncthreads();
    }

    // Epilogue
    const int matrix = FUSED ? (n0 >> 10) : 0;
    const float* bias = FUSED ? (matrix == 0 ? bias0 : (matrix == 1 ? bias1 : bias2))
                              : bias0;
    const int tg = lane >> 2;
    const int tc = (lane & 3) * 2;
#pragma unroll
    for (int mt = 0; mt < 2; mt++) {
#pragma unroll
        for (int nt = 0; nt < 4; nt++) {
            const int n = n0 + wn + nt * 8 + tc;
            const int nl = n & 1023;
            const float b0 = bias[nl], b1 = bias[nl + 1];
#pragma unroll
            for (int hf = 0; hf < 2; hf++) {
                const int m = m0 + wm + mt * 16 + tg + hf * 8;
                float v0 = acc[mt][nt][hf * 2 + 0] + b0;
                float v1 = acc[mt][nt][hf * 2 + 1] + b1;
                if (!FUSED) {
                    *(float2*)(o_f32 + (size_t)m * Dd + n) = make_float2(v0, v1);
                } else {
                    const int bi = m >> 11, sr = m & 2047;
                    const int hh = nl >> 6, hd = nl & 63;
                    if (matrix == 0) {          // Q: scaled, fp16 hi/lo
                        v0 *= QSCALE; v1 *= QSCALE;
                        const size_t a = (((size_t)(bi * Hh + hh)) * Ss + sr) * HDd + hd;
                        __half h0, h1, l0, l1;
                        split1(v0, h0, l0); split1(v1, h1, l1);
                        __half2 ph = __halves2half2(h0, h1);
                        __half2 pl = __halves2half2(l0, l1);
                        *(uint32_t*)(o_qh + a) = *(uint32_t*)&ph;
                        *(uint32_t*)(o_ql + a) = *(uint32_t*)&pl;
                    } else if (matrix == 1) {   // K: fp16
                        const size_t a = (((size_t)(bi * Hh + hh)) * Ss + sr) * HDd + hd;
                        __half2 ph = __floats2half2_rn(v0, v1);
                        *(uint32_t*)(o_k + a) = *(uint32_t*)&ph;
                    } else {                    // V: fp16 transposed [B,H,HD,S]
                        const size_t a = (((size_t)(bi * Hh + hh)) * HDd + hd) * Ss + sr;
                        o_vt[a]      = __float2half(v0);
                        o_vt[a + Ss] = __float2half(v1);
                    }
                }
            }
        }
    }
}

// ---------------------------------------------------------------------------
// Tensor-core flash attention (R11 version — 2-pass fp16 QK^T, 2 CTAs/SM).
// CTA: 128 q rows; 8 warps x 16 q rows. KV tile 128.
// QK^T: Q hi/lo, frags reloaded per kc. PV: fp16.
// Softmax in c-frags, exp2 domain. ctx written as plain fp16 [B,S,D].
// ---------------------------------------------------------------------------
#define QROW 144
#define VROW 272
#define QMAT (128 * QROW)
#define KMAT (128 * QROW)
#define VMAT (64 * VROW)
#define STAGEA (KMAT + VMAT)
#define ATT_SMEM (2 * QMAT + 2 * STAGEA)  // 108544

__device__ __forceinline__ void attn_load_kv(
    uint32_t st, int tid, int kv0,
    const __half* __restrict__ kp, const __half* __restrict__ vt,
    size_t qkbase, size_t vbase)
{
#pragma unroll
    for (int i = 0; i < 4; i++) {
        int idx = tid + i * 256;
        int r = idx >> 3, c = (idx & 7) * 8;
        cp16(st + r * QROW + c * 2, kp + qkbase + (size_t)(kv0 + r) * HDd + c);
    }
#pragma unroll
    for (int i = 0; i < 4; i++) {
        int idx = tid + i * 256;
        int r = idx >> 4, c = (idx & 15) * 8;
        cp16(st + KMAT + r * VROW + c * 2, vt + vbase + (size_t)r * Ss + kv0 + c);
    }
}

__global__ __launch_bounds__(256, 2)
void attn_tc(const __half* __restrict__ qh, const __half* __restrict__ ql,
             const __half* __restrict__ kp, const __half* __restrict__ vt,
             __half* __restrict__ cp)
{
    extern __shared__ char sm[];
    const uint32_t sb = smem_u32(sm);
    const int tid = threadIdx.x;
    const int w = tid >> 5, lane = tid & 31;
    const int q0 = blockIdx.x * 128;
    const int h = blockIdx.y, b = blockIdx.z;
    const size_t qkbase = ((size_t)(b * Hh + h) * Ss) * HDd;
    const size_t vbase  = ((size_t)(b * Hh + h) * HDd) * Ss;

    // Prologue: Q hi/lo (resident in smem) + KV tile 0
#pragma unroll
    for (int i = 0; i < 4; i++) {
        int idx = tid + i * 256;
        int r = idx >> 3, c = (idx & 7) * 8;
        cp16(sb + r * QROW + c * 2,        qh + qkbase + (size_t)(q0 + r) * HDd + c);
        cp16(sb + QMAT + r * QROW + c * 2, ql + qkbase + (size_t)(q0 + r) * HDd + c);
    }
    attn_load_kv(sb + 2 * QMAT, tid, 0, kp, vt, qkbase, vbase);
    CP_COMMIT();

    const int a_r = lane & 15;
    const int a_k = (lane >> 4) * 8;
    const int b_r = (lane & 7) + ((lane >> 4) << 3);
    const int b_k = (lane & 8) ? 8 : 0;

    float o[8][4];
#pragma unroll
    for (int nt = 0; nt < 8; nt++)
#pragma unroll
        for (int i = 0; i < 4; i++) o[nt][i] = 0.f;
    float m2[2] = {-1e30f, -1e30f};
    float lsum[2] = {0.f, 0.f};

    for (int t = 0; t < Ss / 128; t++) {
        const int s = t & 1;
        const uint32_t stc = sb + 2 * QMAT + s * STAGEA;
        if (t + 1 < Ss / 128) {
            attn_load_kv(sb + 2 * QMAT + (s ^ 1) * STAGEA, tid, (t + 1) * 128,
                         kp, vt, qkbase, vbase);
            CP_COMMIT();
            CP_WAIT1();
        } else {
            CP_WAIT0();
        }
        __syncthreads();

        // ---- scores S = Q K^T (2-pass fp16; Q frags reloaded per kc) ----
        float sc[16][4];
#pragma unroll
        for (int nt = 0; nt < 16; nt++)
#pragma unroll
            for (int i = 0; i < 4; i++) sc[nt][i] = 0.f;

#pragma unroll
        for (int kc = 0; kc < 4; kc++) {
            uint32_t qf[4], qlf[4];
            uint32_t qad = sb + (w * 16 + a_r) * QROW + (kc * 16 + a_k) * 2;
            ldsm_x4(qad, qf);
            ldsm_x4(qad + QMAT, qlf);
#pragma unroll
            for (int g = 0; g < 8; g++) {
                uint32_t bh[4];
                uint32_t ad = stc + (g * 16 + b_r) * QROW + (kc * 16 + b_k) * 2;
                ldsm_x4(ad, bh);
                mma16816h(sc[2 * g],     qf,  bh);
                mma16816h(sc[2 * g],     qlf, bh);
                mma16816h(sc[2 * g + 1], qf,  bh + 2);
                mma16816h(sc[2 * g + 1], qlf, bh + 2);
            }
        }

        // ---- online softmax (exp2 domain; rows split over 4-lane groups) ----
#pragma unroll
        for (int rh = 0; rh < 2; rh++) {
            const int c0 = rh * 2;
            float mx = -1e30f;
#pragma unroll
            for (int nt = 0; nt < 16; nt++)
                mx = fmaxf(mx, fmaxf(sc[nt][c0], sc[nt][c0 + 1]));
            mx = fmaxf(mx, __shfl_xor_sync(0xffffffffu, mx, 1));
            mx = fmaxf(mx, __shfl_xor_sync(0xffffffffu, mx, 2));
            float mn = fmaxf(m2[rh], mx);
            float al = ex2(m2[rh] - mn);
            m2[rh] = mn;
            float rs = 0.f;
#pragma unroll
            for (int nt = 0; nt < 16; nt++) {
                sc[nt][c0]     = ex2(sc[nt][c0] - mn);
                sc[nt][c0 + 1] = ex2(sc[nt][c0 + 1] - mn);
                rs += sc[nt][c0] + sc[nt][c0 + 1];
            }
            rs += __shfl_xor_sync(0xffffffffu, rs, 1);
            rs += __shfl_xor_sync(0xffffffffu, rs, 2);
            lsum[rh] = lsum[rh] * al + rs;
#pragma unroll
            for (int nt = 0; nt < 8; nt++) {
                o[nt][c0]     *= al;
                o[nt][c0 + 1] *= al;
            }
        }

        // ---- P (c-frag) -> fp16 A-frags, register-only ----
        uint32_t pa[8][4];
#pragma unroll
        for (int kc = 0; kc < 8; kc++) {
            pa[kc][0] = pack_h2(sc[2 * kc][0],     sc[2 * kc][1]);
            pa[kc][1] = pack_h2(sc[2 * kc][2],     sc[2 * kc][3]);
            pa[kc][2] = pack_h2(sc[2 * kc + 1][0], sc[2 * kc + 1][1]);
            pa[kc][3] = pack_h2(sc[2 * kc + 1][2], sc[2 * kc + 1][3]);
        }

        // ---- O += P V (fp16) ----
        const uint32_t vs = stc + KMAT;
#pragma unroll
        for (int g = 0; g < 4; g++) {
#pragma unroll
            for (int kc = 0; kc < 8; kc++) {
                uint32_t vb[4];
                ldsm_x4(vs + (g * 16 + b_r) * VROW + (kc * 16 + b_k) * 2, vb);
                mma16816h(o[2 * g],     pa[kc], vb);
                mma16816h(o[2 * g + 1], pa[kc], vb + 2);
            }
        }
        __syncthreads();
    }

    // ---- epilogue: ctx = O/l as plain fp16, [B,S,D] layout ----
    const int tg = lane >> 2;
    const int tc2 = (lane & 3) * 2;
#pragma unroll
    for (int rh = 0; rh < 2; rh++) {
        float inv = 1.f / lsum[rh];
        int srow = q0 + w * 16 + tg + rh * 8;
#pragma unroll
        for (int nt = 0; nt < 8; nt++) {
            float v0 = o[nt][rh * 2] * inv;
            float v1 = o[nt][rh * 2 + 1] * inv;
            __half2 ph = __floats2half2_rn(v0, v1);
            size_t a = ((size_t)b * Ss + srow) * Dd + h * HDd + nt * 8 + tc2;
            *(uint32_t*)(cp + a) = *(uint32_t*)&ph;
        }
    }
}

// ---------------------------------------------------------------------------
extern "C" void kernel_launch(void* const* d_in, const int* in_sizes, int n_in,
                              void* d_out, int out_size)
{
    const float* x  = (const float*)d_in[0];
    const float* Wq = (const float*)d_in[1];
    const float* bq = (const float*)d_in[2];
    const float* Wk = (const float*)d_in[3];
    const float* bk = (const float*)d_in[4];
    const float* Wv = (const float*)d_in[5];
    const float* bv = (const float*)d_in[6];
    const float* Wo = (const float*)d_in[7];
    const float* bo = (const float*)d_in[8];
    float* out = (float*)d_out;

    __half *xh, *xl, *wp, *qhp, *qlp, *kpp, *vtp, *cpp;
    cudaGetSymbolAddress((void**)&xh,  g_xh);
    cudaGetSymbolAddress((void**)&xl,  g_xl);
    cudaGetSymbolAddress((void**)&wp,  g_w);
    cudaGetSymbolAddress((void**)&qhp, g_qh);
    cudaGetSymbolAddress((void**)&qlp, g_ql);
    cudaGetSymbolAddress((void**)&kpp, g_k);
    cudaGetSymbolAddress((void**)&vtp, g_vt);
    cudaGetSymbolAddress((void**)&cpp, g_c);

    cudaFuncSetAttribute((const void*)gemm_tc<1, 1>,
                         cudaFuncAttributeMaxDynamicSharedMemorySize, GSMEM);
    cudaFuncSetAttribute((const void*)gemm_tc<0, 0>,
                         cudaFuncAttributeMaxDynamicSharedMemorySize, GSMEM);
    cudaFuncSetAttribute(attn_tc,
                         cudaFuncAttributeMaxDynamicSharedMemorySize, ATT_SMEM);

    // conversions
    const int nx4 = (Mm * Dd) / 4;
    const int nw4 = (Dd * Dd) / 4;
    split_x<<<nx4 / 256, 256>>>((const float4*)x, (uint2*)xh, (uint2*)xl, nx4);
    dim3 gw(nw4 / 256, 4);
    cast_w4<<<gw, 256>>>((const float4*)Wq, (const float4*)Wk,
                         (const float4*)Wv, (const float4*)Wo, (uint2*)wp, nw4);

    // fused QKV projection: N = 3072 (2-pass fp16)
    dim3 gf(3 * Dd / 128, Mm / 128);   // (24, 64)
    gemm_tc<1, 1><<<gf, 512, GSMEM>>>(xh, xl, wp, bq, bk, bv,
                                      qhp, qlp, kpp, vtp, nullptr);

    // attention (R11 kernel, plain-fp16 ctx epilogue)
    dim3 ga(Ss / 128, Hh, Bb);         // (16, 16, 4)
    attn_tc<<<ga, 256, ATT_SMEM>>>(qhp, qlp, kpp, vtp, cpp);

    // output projection (single-pass fp16)
    dim3 go(Dd / 128, Mm / 128);       // (8, 64)
    gemm_tc<0, 0><<<go, 512, GSMEM>>>(cpp, nullptr, wp + 3 * (size_t)Dd * Dd,
                                      bo, nullptr, nullptr,
                                      nullptr, nullptr, nullptr, nullptr, out);
}